// round 4
// baseline (speedup 1.0000x reference)
#include <cuda_runtime.h>
#include <cstdint>

#define Nn 8192
#define Dd 1024
#define MARGINc 1.0f
#define EPSc 1e-6f

// ---------------- scratch (static __device__ globals, allowed) ----------------
__device__ float g_sq[Nn];
__device__ float g_Dmat[(size_t)Nn * Nn];          // 256 MB distance matrix
__device__ unsigned long long g_pos[Nn];           // packed (dist_bits<<32)|~j
__device__ float g_dp[Nn];
__device__ int   g_posidx[Nn];
__device__ int   g_negidx[Nn];
__device__ float g_rowloss[Nn];

// ---------------- K1: row squared norms + reset g_pos ----------------
__global__ __launch_bounds__(256) void sq_kernel(const float* __restrict__ emb) {
    int row  = blockIdx.x * 8 + (threadIdx.x >> 5);
    int lane = threadIdx.x & 31;
    const float* p = emb + (size_t)row * Dd;
    float s = 0.f;
    #pragma unroll
    for (int k = lane * 4; k < Dd; k += 128) {
        float4 v = *(const float4*)(p + k);
        s += v.x * v.x + v.y * v.y + v.z * v.z + v.w * v.w;
    }
    #pragma unroll
    for (int off = 16; off; off >>= 1) s += __shfl_xor_sync(0xffffffffu, s, off);
    if (lane == 0) { g_sq[row] = s; g_pos[row] = 0ULL; }
}

// ---------------- K2: fp32 tiled GEMM -> distances + hardest-positive ----------------
// Block tile 128x128, K-step 8, 256 threads, 8x8 micro-tile per thread.
#define BM 128
#define BN 128
#define BK 8
#define PADW 132

__global__ __launch_bounds__(256) void gemm_pos_kernel(const float* __restrict__ emb,
                                                       const int*   __restrict__ tgt) {
    __shared__ __align__(16) float As[BK][PADW];
    __shared__ __align__(16) float Bs[BK][PADW];

    const int rowBase = blockIdx.y * BM;
    const int colBase = blockIdx.x * BN;
    const int tid = threadIdx.x;
    const int tx = tid & 15;
    const int ty = tid >> 4;

    float acc[8][8];
    #pragma unroll
    for (int r = 0; r < 8; r++)
        #pragma unroll
        for (int c = 0; c < 8; c++) acc[r][c] = 0.f;

    const int lr = tid >> 1;          // 0..127 : tile row
    const int lk = (tid & 1) * 4;     // 0 or 4 : k offset
    const float* Aptr = emb + (size_t)(rowBase + lr) * Dd + lk;
    const float* Bptr = emb + (size_t)(colBase + lr) * Dd + lk;

    for (int k0 = 0; k0 < Dd; k0 += BK) {
        float4 av = *(const float4*)(Aptr + k0);
        float4 bv = *(const float4*)(Bptr + k0);
        __syncthreads();
        As[lk + 0][lr] = av.x; As[lk + 1][lr] = av.y;
        As[lk + 2][lr] = av.z; As[lk + 3][lr] = av.w;
        Bs[lk + 0][lr] = bv.x; Bs[lk + 1][lr] = bv.y;
        Bs[lk + 2][lr] = bv.z; Bs[lk + 3][lr] = bv.w;
        __syncthreads();
        #pragma unroll
        for (int kk = 0; kk < BK; kk++) {
            float4 a0 = *(const float4*)&As[kk][ty * 8];
            float4 a1 = *(const float4*)&As[kk][ty * 8 + 4];
            float4 b0 = *(const float4*)&Bs[kk][tx * 8];
            float4 b1 = *(const float4*)&Bs[kk][tx * 8 + 4];
            float a[8] = {a0.x, a0.y, a0.z, a0.w, a1.x, a1.y, a1.z, a1.w};
            float b[8] = {b0.x, b0.y, b0.z, b0.w, b1.x, b1.y, b1.z, b1.w};
            #pragma unroll
            for (int r = 0; r < 8; r++)
                #pragma unroll
                for (int c = 0; c < 8; c++)
                    acc[r][c] = fmaf(a[r], b[c], acc[r][c]);
        }
    }

    // epilogue: distances, store row-major, fused hardest-positive argmax
    const int gi0 = rowBase + ty * 8;
    const int gj0 = colBase + tx * 8;
    float sqi[8], sqj[8];
    int   ci[8],  cj[8];
    #pragma unroll
    for (int r = 0; r < 8; r++) { sqi[r] = g_sq[gi0 + r]; ci[r] = tgt[gi0 + r]; }
    #pragma unroll
    for (int c = 0; c < 8; c++) { sqj[c] = g_sq[gj0 + c]; cj[c] = tgt[gj0 + c]; }

    #pragma unroll
    for (int r = 0; r < 8; r++) {
        const int gi = gi0 + r;
        float dv[8];
        unsigned long long best = 0ULL;
        #pragma unroll
        for (int c = 0; c < 8; c++) {
            float d2 = sqi[r] + sqj[c] - 2.f * acc[r][c];
            float d  = sqrtf(fmaxf(d2, 0.f));
            dv[c] = d;
            const int gj = gj0 + c;
            if (ci[r] == cj[c] && gi != gj) {
                unsigned long long key =
                    ((unsigned long long)__float_as_uint(d) << 32) | (unsigned)(~gj);
                if (key > best) best = key;
            }
        }
        float* outp = &g_Dmat[(size_t)gi * Nn + gj0];
        *(float4*)(outp)     = make_float4(dv[0], dv[1], dv[2], dv[3]);
        *(float4*)(outp + 4) = make_float4(dv[4], dv[5], dv[6], dv[7]);
        // reduce across the 16 tx lanes sharing this row block (stays within half-warp)
        #pragma unroll
        for (int off = 8; off >= 1; off >>= 1) {
            unsigned long long o = __shfl_xor_sync(0xffffffffu, best, off);
            if (o > best) best = o;
        }
        if (tx == 0 && best) atomicMax(&g_pos[gi], best);
    }
}

// ---------------- K3: unpack hardest positive ----------------
__global__ void pos_extract_kernel() {
    int i = blockIdx.x * 256 + threadIdx.x;
    unsigned long long key = g_pos[i];
    if (key == 0ULL) { g_dp[i] = -1e9f; g_posidx[i] = 0; }  // no positive: match ref fallback
    else {
        g_dp[i]     = __uint_as_float((unsigned)(key >> 32));
        g_posidx[i] = (int)(~(unsigned)key);
    }
}

// ---------------- K4: semi-hard / hardest negative per row ----------------
__global__ __launch_bounds__(256) void neg_kernel(const int* __restrict__ tgt) {
    const int i   = blockIdx.x;
    const int cls = tgt[i];
    const float dp = g_dp[i];
    const float hi = dp + MARGINc;
    unsigned long long semi = ~0ULL, hard = ~0ULL;
    const float* row = &g_Dmat[(size_t)i * Nn];
    for (int j = threadIdx.x; j < Nn; j += 256) {
        if (tgt[j] != cls) {
            float d = row[j];
            unsigned long long key =
                ((unsigned long long)__float_as_uint(d) << 32) | (unsigned)j;
            if (key < hard) hard = key;
            if (d > dp && d < hi && key < semi) semi = key;
        }
    }
    __shared__ unsigned long long sS[256], sH[256];
    sS[threadIdx.x] = semi; sH[threadIdx.x] = hard;
    __syncthreads();
    for (int s = 128; s; s >>= 1) {
        if (threadIdx.x < s) {
            if (sS[threadIdx.x + s] < sS[threadIdx.x]) sS[threadIdx.x] = sS[threadIdx.x + s];
            if (sH[threadIdx.x + s] < sH[threadIdx.x]) sH[threadIdx.x] = sH[threadIdx.x + s];
        }
        __syncthreads();
    }
    if (threadIdx.x == 0) {
        unsigned long long k = (sS[0] != ~0ULL) ? sS[0] : sH[0];
        g_negidx[i] = (int)(unsigned)k;
    }
}

// ---------------- K5: per-row triplet loss (exact torch eps formula) ----------------
__global__ __launch_bounds__(256) void loss_kernel(const float* __restrict__ emb) {
    const int i = blockIdx.x;
    const float* a = emb + (size_t)i * Dd;
    const float* p = emb + (size_t)g_posidx[i] * Dd;
    const float* n = emb + (size_t)g_negidx[i] * Dd;
    const int k = threadIdx.x * 4;   // 256*4 = 1024 exactly
    float4 av = *(const float4*)(a + k);
    float4 pv = *(const float4*)(p + k);
    float4 nv = *(const float4*)(n + k);
    float sp = 0.f, sn = 0.f, d;
    d = av.x - pv.x + EPSc; sp += d * d;
    d = av.y - pv.y + EPSc; sp += d * d;
    d = av.z - pv.z + EPSc; sp += d * d;
    d = av.w - pv.w + EPSc; sp += d * d;
    d = av.x - nv.x + EPSc; sn += d * d;
    d = av.y - nv.y + EPSc; sn += d * d;
    d = av.z - nv.z + EPSc; sn += d * d;
    d = av.w - nv.w + EPSc; sn += d * d;

    __shared__ float ssp[256], ssn[256];
    ssp[threadIdx.x] = sp; ssn[threadIdx.x] = sn;
    __syncthreads();
    for (int s = 128; s; s >>= 1) {
        if (threadIdx.x < s) {
            ssp[threadIdx.x] += ssp[threadIdx.x + s];
            ssn[threadIdx.x] += ssn[threadIdx.x + s];
        }
        __syncthreads();
    }
    if (threadIdx.x == 0)
        g_rowloss[i] = fmaxf(sqrtf(ssp[0]) - sqrtf(ssn[0]) + MARGINc, 0.f);
}

// ---------------- K6: deterministic mean reduction ----------------
__global__ __launch_bounds__(1024) void final_kernel(float* __restrict__ out) {
    __shared__ float s[1024];
    const int t = threadIdx.x;
    float v = 0.f;
    #pragma unroll
    for (int b = 0; b < 8; b++) v += g_rowloss[t + b * 1024];
    s[t] = v;
    __syncthreads();
    for (int w = 512; w; w >>= 1) {
        if (t < w) s[t] += s[t + w];
        __syncthreads();
    }
    if (t == 0) out[0] = s[0] / (float)Nn;
}

// ---------------- launch ----------------
extern "C" void kernel_launch(void* const* d_in, const int* in_sizes, int n_in,
                              void* d_out, int out_size) {
    const float* emb = (const float*)d_in[0];
    const int*   tgt = (const int*)d_in[1];
    float* out = (float*)d_out;

    sq_kernel<<<Nn / 8, 256>>>(emb);
    dim3 grid(Nn / BN, Nn / BM);
    gemm_pos_kernel<<<grid, 256>>>(emb, tgt);
    pos_extract_kernel<<<Nn / 256, 256>>>();
    neg_kernel<<<Nn, 256>>>(tgt);
    loss_kernel<<<Nn, 256>>>(emb);
    final_kernel<<<1, 1024>>>(out);
}

// round 14
// speedup vs baseline: 2.3830x; 2.3830x over previous
#include <cuda_runtime.h>
#include <cuda_bf16.h>
#include <cstdint>

#define Nn 8192
#define Dd 1024
#define MARGINc 1.0f
#define EPSc 1e-6f

// ---------------- scratch (static __device__ globals, allowed) ----------------
__device__ float g_sq[Nn];
__device__ float g_Dmat[(size_t)Nn * Nn];          // 256 MB distance matrix
__device__ unsigned long long g_pos[Nn];           // packed (dist_bits<<32)|~j
__device__ float g_dp[Nn];
__device__ int   g_posidx[Nn];
__device__ int   g_negidx[Nn];
__device__ float g_rowloss[Nn];
__device__ __nv_bfloat16 g_hi[(size_t)Nn * Dd];    // 16 MB
__device__ __nv_bfloat16 g_lo[(size_t)Nn * Dd];    // 16 MB

__device__ __forceinline__ uint32_t smem_u32(const void* p) {
    uint32_t a;
    asm("{ .reg .u64 t; cvta.to.shared.u64 t, %1; cvt.u32.u64 %0, t; }" : "=r"(a) : "l"(p));
    return a;
}

// ---------------- K0: fp32 -> (bf16 hi, bf16 lo) split ----------------
__global__ __launch_bounds__(256) void conv_kernel(const float* __restrict__ emb) {
    size_t i = (size_t)blockIdx.x * 256 + threadIdx.x;   // one float4 per thread
    float4 v = ((const float4*)emb)[i];
    __nv_bfloat16 h0 = __float2bfloat16_rn(v.x);
    __nv_bfloat16 h1 = __float2bfloat16_rn(v.y);
    __nv_bfloat16 h2 = __float2bfloat16_rn(v.z);
    __nv_bfloat16 h3 = __float2bfloat16_rn(v.w);
    __nv_bfloat16 l0 = __float2bfloat16_rn(v.x - __bfloat162float(h0));
    __nv_bfloat16 l1 = __float2bfloat16_rn(v.y - __bfloat162float(h1));
    __nv_bfloat16 l2 = __float2bfloat16_rn(v.z - __bfloat162float(h2));
    __nv_bfloat16 l3 = __float2bfloat16_rn(v.w - __bfloat162float(h3));
    __nv_bfloat162 hp0(h0, h1), hp1(h2, h3), lp0(l0, l1), lp1(l2, l3);
    uint2 hw, lw;
    hw.x = *(uint32_t*)&hp0; hw.y = *(uint32_t*)&hp1;
    lw.x = *(uint32_t*)&lp0; lw.y = *(uint32_t*)&lp1;
    ((uint2*)g_hi)[i] = hw;
    ((uint2*)g_lo)[i] = lw;
}

// ---------------- K1: row squared norms + reset g_pos ----------------
__global__ __launch_bounds__(256) void sq_kernel(const float* __restrict__ emb) {
    int row  = blockIdx.x * 8 + (threadIdx.x >> 5);
    int lane = threadIdx.x & 31;
    const float* p = emb + (size_t)row * Dd;
    float s = 0.f;
    #pragma unroll
    for (int k = lane * 4; k < Dd; k += 128) {
        float4 v = *(const float4*)(p + k);
        s += v.x * v.x + v.y * v.y + v.z * v.z + v.w * v.w;
    }
    #pragma unroll
    for (int off = 16; off; off >>= 1) s += __shfl_xor_sync(0xffffffffu, s, off);
    if (lane == 0) { g_sq[row] = s; g_pos[row] = 0ULL; }
}

// ---------------- K2: HMMA (mma.sync bf16, 3-term split) GEMM ----------------
// CTA tile 256x128, K-tile 32 bf16, virtual K = 3 x 1024 (hi*hi, lo*hi, hi*lo).
// 256 threads = 8 warps, warp grid 4(m) x 2(n), warp tile 64x64.
#define BM 256
#define BN 128
#define NKT 96           // 3 * (1024/32)

// smem layout (dynamic): A[2]:16KB each, B[2]:8KB each, staging 1KB
#define SA(buf) ((buf) * 16384u)
#define SB(buf) (32768u + (buf) * 8192u)
#define SSTAGE  49152u
#define SMEM_TOTAL (49152 + 1024)

// 16B-chunk swizzled offset inside a [rows][32 bf16] tile (64B rows)
__device__ __forceinline__ uint32_t swz(uint32_t r, uint32_t c) {
    return r * 64u + ((c ^ ((r >> 1) & 3u)) * 16u);
}
__device__ __forceinline__ void cp16(uint32_t dst, const void* src) {
    asm volatile("cp.async.cg.shared.global [%0], [%1], 16;" :: "r"(dst), "l"(src) : "memory");
}
__device__ __forceinline__ void ldmx4(uint32_t* r, uint32_t addr) {
    asm volatile("ldmatrix.sync.aligned.m8n8.x4.shared.b16 {%0,%1,%2,%3}, [%4];"
                 : "=r"(r[0]), "=r"(r[1]), "=r"(r[2]), "=r"(r[3]) : "r"(addr));
}
__device__ __forceinline__ void mma16816(float* c, const uint32_t* a, uint32_t b0, uint32_t b1) {
    asm volatile(
        "mma.sync.aligned.m16n8k16.row.col.f32.bf16.bf16.f32 "
        "{%0,%1,%2,%3}, {%4,%5,%6,%7}, {%8,%9}, {%0,%1,%2,%3};"
        : "+f"(c[0]), "+f"(c[1]), "+f"(c[2]), "+f"(c[3])
        : "r"(a[0]), "r"(a[1]), "r"(a[2]), "r"(a[3]), "r"(b0), "r"(b1));
}

__device__ __forceinline__ void load_tile(uint32_t sb, int buf, int kt,
                                          int rowBase, int colBase, int tid) {
    const int seg = kt >> 5;                  // 0,1,2
    const int k0  = (kt & 31) << 5;           // bf16 index within 1024
    const __nv_bfloat16* pa = (seg == 1) ? g_lo : g_hi;
    const __nv_bfloat16* pb = (seg == 2) ? g_lo : g_hi;
    #pragma unroll
    for (int it = 0; it < 4; it++) {          // A: 256 rows x 4 chunks
        int id = it * 256 + tid;
        int r = id >> 2, c = id & 3;
        cp16(sb + SA(buf) + swz(r, c), pa + (size_t)(rowBase + r) * Dd + k0 + c * 8);
    }
    #pragma unroll
    for (int it = 0; it < 2; it++) {          // B: 128 rows x 4 chunks
        int id = it * 256 + tid;
        int r = id >> 2, c = id & 3;
        cp16(sb + SB(buf) + swz(r, c), pb + (size_t)(colBase + r) * Dd + k0 + c * 8);
    }
}

__global__ __launch_bounds__(256, 1) void gemm_mma_kernel(const int* __restrict__ tgt) {
    extern __shared__ char smem[];
    const uint32_t sb = smem_u32(smem);
    const int tid  = threadIdx.x;
    const int lane = tid & 31;
    const int wid  = tid >> 5;
    const int wm   = wid & 3;                 // 0..3 (m)
    const int wn   = wid >> 2;                // 0..1 (n)
    const int rowBase = blockIdx.y * BM;
    const int colBase = blockIdx.x * BN;

    int*   cjs  = (int*)(smem + SSTAGE);
    float* sqjs = (float*)(smem + SSTAGE + 512);
    if (tid < BN) { cjs[tid] = tgt[colBase + tid]; sqjs[tid] = g_sq[colBase + tid]; }

    float acc[4][8][4];
    #pragma unroll
    for (int i = 0; i < 4; i++)
        #pragma unroll
        for (int j = 0; j < 8; j++)
            #pragma unroll
            for (int q = 0; q < 4; q++) acc[i][j][q] = 0.f;

    // per-lane ldmatrix address components
    const uint32_t la_row = wm * 64 + ((lane >> 3) & 1) * 8 + (lane & 7);
    const uint32_t la_c   = lane >> 4;                 // 0..1
    const uint32_t maskA  = (la_row >> 1) & 3u;
    const uint32_t lb_row = wn * 64 + (lane >> 4) * 8 + (lane & 7);
    const uint32_t lb_c   = (lane >> 3) & 1;
    const uint32_t maskB  = (lb_row >> 1) & 3u;

    // prologue
    load_tile(sb, 0, 0, rowBase, colBase, tid);
    asm volatile("cp.async.commit_group;" ::: "memory");

    for (int kt = 0; kt < NKT; kt++) {
        const int cur = kt & 1;
        if (kt + 1 < NKT) {
            load_tile(sb, cur ^ 1, kt + 1, rowBase, colBase, tid);
            asm volatile("cp.async.commit_group;" ::: "memory");
            asm volatile("cp.async.wait_group 1;" ::: "memory");
        } else {
            asm volatile("cp.async.wait_group 0;" ::: "memory");
        }
        __syncthreads();

        const uint32_t aBase = sb + SA(cur) + la_row * 64;
        const uint32_t bBase = sb + SB(cur) + lb_row * 64;
        #pragma unroll
        for (int h = 0; h < 2; h++) {
            uint32_t aR[4][4], bR[4][4];
            #pragma unroll
            for (int i = 0; i < 4; i++)
                ldmx4(aR[i], aBase + i * 1024 + (((2 * h + la_c) ^ maskA) * 16));
            #pragma unroll
            for (int jg = 0; jg < 4; jg++)
                ldmx4(bR[jg], bBase + jg * 1024 + (((2 * h + lb_c) ^ maskB) * 16));
            #pragma unroll
            for (int i = 0; i < 4; i++)
                #pragma unroll
                for (int j = 0; j < 8; j++)
                    mma16816(acc[i][j], aR[i], bR[j >> 1][(j & 1) * 2], bR[j >> 1][(j & 1) * 2 + 1]);
        }
        __syncthreads();
    }

    // ---------------- epilogue: d = sqrt(sqi+sqj-2S), store, hardest positive ----------------
    const int r0base = rowBase + wm * 64 + (lane >> 2);
    const int cbase  = colBase + wn * 64 + (lane & 3) * 2;

    #pragma unroll
    for (int i = 0; i < 4; i++) {
        const int gi0 = r0base + i * 16;
        const int gi1 = gi0 + 8;
        const float sq0 = g_sq[gi0], sq1 = g_sq[gi1];
        const int c0 = tgt[gi0], c1 = tgt[gi1];
        unsigned long long best0 = 0ULL, best1 = 0ULL;
        #pragma unroll
        for (int j = 0; j < 8; j++) {
            const int gj = cbase + j * 8;
            const int jl = gj - colBase;
            const float sja = sqjs[jl], sjb = sqjs[jl + 1];
            const int cja = cjs[jl], cjb = cjs[jl + 1];
            float d00 = sqrtf(fmaxf(sq0 + sja - 2.f * acc[i][j][0], 0.f));
            float d01 = sqrtf(fmaxf(sq0 + sjb - 2.f * acc[i][j][1], 0.f));
            float d10 = sqrtf(fmaxf(sq1 + sja - 2.f * acc[i][j][2], 0.f));
            float d11 = sqrtf(fmaxf(sq1 + sjb - 2.f * acc[i][j][3], 0.f));
            *(float2*)&g_Dmat[(size_t)gi0 * Nn + gj] = make_float2(d00, d01);
            *(float2*)&g_Dmat[(size_t)gi1 * Nn + gj] = make_float2(d10, d11);
            if (c0 == cja && gi0 != gj) {
                unsigned long long k = ((unsigned long long)__float_as_uint(d00) << 32) | (unsigned)(~gj);
                if (k > best0) best0 = k;
            }
            if (c0 == cjb && gi0 != gj + 1) {
                unsigned long long k = ((unsigned long long)__float_as_uint(d01) << 32) | (unsigned)(~(gj + 1));
                if (k > best0) best0 = k;
            }
            if (c1 == cja && gi1 != gj) {
                unsigned long long k = ((unsigned long long)__float_as_uint(d10) << 32) | (unsigned)(~gj);
                if (k > best1) best1 = k;
            }
            if (c1 == cjb && gi1 != gj + 1) {
                unsigned long long k = ((unsigned long long)__float_as_uint(d11) << 32) | (unsigned)(~(gj + 1));
                if (k > best1) best1 = k;
            }
        }
        // reduce across the 4 lanes sharing these rows (consecutive lanes, quad)
        #pragma unroll
        for (int off = 1; off <= 2; off <<= 1) {
            unsigned long long o0 = __shfl_xor_sync(0xffffffffu, best0, off);
            if (o0 > best0) best0 = o0;
            unsigned long long o1 = __shfl_xor_sync(0xffffffffu, best1, off);
            if (o1 > best1) best1 = o1;
        }
        if ((lane & 3) == 0) {
            if (best0) atomicMax(&g_pos[gi0], best0);
            if (best1) atomicMax(&g_pos[gi1], best1);
        }
    }
}

// ---------------- K3: unpack hardest positive ----------------
__global__ void pos_extract_kernel() {
    int i = blockIdx.x * 256 + threadIdx.x;
    unsigned long long key = g_pos[i];
    if (key == 0ULL) { g_dp[i] = -1e9f; g_posidx[i] = 0; }
    else {
        g_dp[i]     = __uint_as_float((unsigned)(key >> 32));
        g_posidx[i] = (int)(~(unsigned)key);
    }
}

// ---------------- K4: semi-hard / hardest negative per row ----------------
__global__ __launch_bounds__(256) void neg_kernel(const int* __restrict__ tgt) {
    const int i   = blockIdx.x;
    const int cls = tgt[i];
    const float dp = g_dp[i];
    const float hi = dp + MARGINc;
    unsigned long long semi = ~0ULL, hard = ~0ULL;
    const float* row = &g_Dmat[(size_t)i * Nn];
    for (int j = threadIdx.x; j < Nn; j += 256) {
        if (tgt[j] != cls) {
            float d = row[j];
            unsigned long long key =
                ((unsigned long long)__float_as_uint(d) << 32) | (unsigned)j;
            if (key < hard) hard = key;
            if (d > dp && d < hi && key < semi) semi = key;
        }
    }
    __shared__ unsigned long long sS[256], sH[256];
    sS[threadIdx.x] = semi; sH[threadIdx.x] = hard;
    __syncthreads();
    for (int s = 128; s; s >>= 1) {
        if (threadIdx.x < s) {
            if (sS[threadIdx.x + s] < sS[threadIdx.x]) sS[threadIdx.x] = sS[threadIdx.x + s];
            if (sH[threadIdx.x + s] < sH[threadIdx.x]) sH[threadIdx.x] = sH[threadIdx.x + s];
        }
        __syncthreads();
    }
    if (threadIdx.x == 0) {
        unsigned long long k = (sS[0] != ~0ULL) ? sS[0] : sH[0];
        g_negidx[i] = (int)(unsigned)k;
    }
}

// ---------------- K5: per-row triplet loss (exact torch eps formula) ----------------
__global__ __launch_bounds__(256) void loss_kernel(const float* __restrict__ emb) {
    const int i = blockIdx.x;
    const float* a = emb + (size_t)i * Dd;
    const float* p = emb + (size_t)g_posidx[i] * Dd;
    const float* n = emb + (size_t)g_negidx[i] * Dd;
    const int k = threadIdx.x * 4;
    float4 av = *(const float4*)(a + k);
    float4 pv = *(const float4*)(p + k);
    float4 nv = *(const float4*)(n + k);
    float sp = 0.f, sn = 0.f, d;
    d = av.x - pv.x + EPSc; sp += d * d;
    d = av.y - pv.y + EPSc; sp += d * d;
    d = av.z - pv.z + EPSc; sp += d * d;
    d = av.w - pv.w + EPSc; sp += d * d;
    d = av.x - nv.x + EPSc; sn += d * d;
    d = av.y - nv.y + EPSc; sn += d * d;
    d = av.z - nv.z + EPSc; sn += d * d;
    d = av.w - nv.w + EPSc; sn += d * d;

    __shared__ float ssp[256], ssn[256];
    ssp[threadIdx.x] = sp; ssn[threadIdx.x] = sn;
    __syncthreads();
    for (int s = 128; s; s >>= 1) {
        if (threadIdx.x < s) {
            ssp[threadIdx.x] += ssp[threadIdx.x + s];
            ssn[threadIdx.x] += ssn[threadIdx.x + s];
        }
        __syncthreads();
    }
    if (threadIdx.x == 0)
        g_rowloss[i] = fmaxf(sqrtf(ssp[0]) - sqrtf(ssn[0]) + MARGINc, 0.f);
}

// ---------------- K6: deterministic mean reduction ----------------
__global__ __launch_bounds__(1024) void final_kernel(float* __restrict__ out) {
    __shared__ float s[1024];
    const int t = threadIdx.x;
    float v = 0.f;
    #pragma unroll
    for (int b = 0; b < 8; b++) v += g_rowloss[t + b * 1024];
    s[t] = v;
    __syncthreads();
    for (int w = 512; w; w >>= 1) {
        if (t < w) s[t] += s[t + w];
        __syncthreads();
    }
    if (t == 0) out[0] = s[0] / (float)Nn;
}

// ---------------- launch ----------------
extern "C" void kernel_launch(void* const* d_in, const int* in_sizes, int n_in,
                              void* d_out, int out_size) {
    const float* emb = (const float*)d_in[0];
    const int*   tgt = (const int*)d_in[1];
    float* out = (float*)d_out;

    cudaFuncSetAttribute(gemm_mma_kernel,
                         cudaFuncAttributeMaxDynamicSharedMemorySize, SMEM_TOTAL);

    conv_kernel<<<(Nn * Dd / 4) / 256, 256>>>(emb);
    sq_kernel<<<Nn / 8, 256>>>(emb);
    dim3 grid(Nn / BN, Nn / BM);
    gemm_mma_kernel<<<grid, 256, SMEM_TOTAL>>>(tgt);
    pos_extract_kernel<<<Nn / 256, 256>>>();
    neg_kernel<<<Nn, 256>>>(tgt);
    loss_kernel<<<Nn, 256>>>(emb);
    final_kernel<<<1, 1024>>>(out);
}